// round 16
// baseline (speedup 1.0000x reference)
#include <cuda_runtime.h>
#include <cuda_fp16.h>
#include <cstdint>

// SubLSTM: T=512, B=64, I=H=1024, L=2, gates (i,o,z), fixed forget fg=sigmoid(f)
//   gates = sigmoid(x W^T + h R^T + bi + bh)
//   c' = c*fg + z - i ;  h' = sigmoid(c') - o
// Output: [out (T*B*H)][h0_fin][h1_fin][c0_fin][c1_fin]
//
// FUSED: stage s does layer0 step s and layer1 step s-1 (513 stages).
// Per-warp cp.async pipelines (disjoint A-fragment slices) -> no intra-stage
// named barriers, only __syncwarp.

#define T_STEPS 512
#define BATCH   64
#define HSZ     1024
#define G3      3072
#define TBH     (T_STEPS * BATCH * HSZ)
#define BH      (BATCH * HSZ)
#define NB      128
#define HSLOTH  (HSZ * BATCH)        // 65536 halves per h slot

// Device-global scratch (allocation-free rule)
__device__ float  g_gx[(size_t)T_STEPS * BATCH * G3];   // [t][3072][64] layer0 Wx+b
// h ping-pong slots, fp16, A-FRAGMENT order for m16n8k16:
//   half idx = kb*1024 + (b>>4)*256 + lane*8 + (hi*4 + hb8*2 + lo)
__device__ __half g_h0s[2 * HSLOTH];
__device__ __half g_h1s[2 * HSLOTH];
__device__ unsigned g_arrive;                 // legacy atomic barrier (init only)
__device__ unsigned g_gen;
__device__ unsigned g_flags[NB * 32];         // per-CTA stage flags, 128B stride

__device__ __forceinline__ float sigf(float x) { return 1.f / (1.f + __expf(-x)); }

// ===================== PTX helpers =====================
__device__ __forceinline__ uint32_t smem_u32(const void* p) {
    uint32_t a;
    asm("{ .reg .u64 t; cvta.to.shared.u64 t, %1; cvt.u32.u64 %0, t; }" : "=r"(a) : "l"(p));
    return a;
}
#define CP_ASYNC16(dst, src) \
    asm volatile("cp.async.ca.shared.global [%0], [%1], 16;" :: "r"(dst), "l"(src) : "memory")
#define CP_ASYNC_CG16(dst, src) \
    asm volatile("cp.async.cg.shared.global [%0], [%1], 16;" :: "r"(dst), "l"(src) : "memory")
#define CP_COMMIT() asm volatile("cp.async.commit_group;" ::: "memory")
#define CPWAIT(n)   asm volatile("cp.async.wait_group %0;" :: "n"(n) : "memory")

__device__ __forceinline__ unsigned ld_acq(const unsigned* p) {
    unsigned v;
    asm volatile("ld.acquire.gpu.u32 %0, [%1];" : "=r"(v) : "l"(p) : "memory");
    return v;
}
__device__ __forceinline__ void st_rel(unsigned* p, unsigned v) {
    asm volatile("st.release.gpu.u32 [%0], %1;" :: "l"(p), "r"(v) : "memory");
}

__device__ __forceinline__ uint32_t f2tf32(float x) {
    uint32_t u;
    asm("cvt.rna.tf32.f32 %0, %1;" : "=r"(u) : "f"(x));
    return u;
}
__device__ __forceinline__ void mma_tf32(float& d0, float& d1, float& d2, float& d3,
                                         uint32_t a0, uint32_t a1, uint32_t a2, uint32_t a3,
                                         uint32_t b0, uint32_t b1) {
    asm volatile("mma.sync.aligned.m16n8k8.row.col.f32.tf32.tf32.f32 "
                 "{%0,%1,%2,%3}, {%4,%5,%6,%7}, {%8,%9}, {%0,%1,%2,%3};"
                 : "+f"(d0), "+f"(d1), "+f"(d2), "+f"(d3)
                 : "r"(a0), "r"(a1), "r"(a2), "r"(a3), "r"(b0), "r"(b1));
}
__device__ __forceinline__ void mma_f16(float& d0, float& d1, float& d2, float& d3,
                                        uint32_t a0, uint32_t a1, uint32_t a2, uint32_t a3,
                                        uint32_t b0, uint32_t b1) {
    asm volatile("mma.sync.aligned.m16n8k16.row.col.f32.f16.f16.f32 "
                 "{%0,%1,%2,%3}, {%4,%5,%6,%7}, {%8,%9}, {%0,%1,%2,%3};"
                 : "+f"(d0), "+f"(d1), "+f"(d2), "+f"(d3)
                 : "r"(a0), "r"(a1), "r"(a2), "r"(a3), "r"(b0), "r"(b1));
}

// Legacy generation barrier (atomic). Used ONCE per launch to fence init.
__device__ __forceinline__ void grid_sync_atomic() {
    __threadfence();
    __syncthreads();
    if (threadIdx.x == 0) {
        unsigned gen = *(volatile unsigned*)&g_gen;
        unsigned t = atomicInc(&g_arrive, NB - 1);
        if (t == NB - 1) {
            __threadfence();
            *(volatile unsigned*)&g_gen = gen + 1;
        } else {
            while (*(volatile unsigned*)&g_gen == gen) { }
        }
        __threadfence();
    }
    __syncthreads();
}

// ---------------------------------------------------------------------------
// TF32 mma.sync GEMM (unchanged, passing) -- layer-0 input gates only
// ---------------------------------------------------------------------------
#define SMPAD 36
__global__ __launch_bounds__(256, 2) void gemm_tf32_kernel(
    const float* __restrict__ A, const float* __restrict__ W,
    const float* __restrict__ bi, const float* __restrict__ bh,
    float* __restrict__ C)
{
    __shared__ float smA[128 * SMPAD];
    __shared__ float smB[128 * SMPAD];

    const int tid = threadIdx.x;
    const int wid = tid >> 5;
    const int lane = tid & 31;
    const int g   = lane >> 2;
    const int tig = lane & 3;
    const int wm  = wid & 3;
    const int wn  = wid >> 2;
    const int m0  = blockIdx.y * 128;
    const int n0  = blockIdx.x * 128;

    const uint32_t sa = smem_u32(smA);
    const uint32_t sb = smem_u32(smB);

    float acc[2][8][4];
#pragma unroll
    for (int mt = 0; mt < 2; mt++)
#pragma unroll
        for (int nt = 0; nt < 8; nt++)
#pragma unroll
            for (int r = 0; r < 4; r++) acc[mt][nt][r] = 0.f;

    const int lrow = tid >> 3;
    const int lq   = tid & 7;

#pragma unroll 1
    for (int kt = 0; kt < HSZ / 32; kt++) {
        const int k0 = kt * 32;
#pragma unroll
        for (int i = 0; i < 4; i++) {
            const int row = lrow + i * 32;
            CP_ASYNC16(sa + (uint32_t)(row * SMPAD + lq * 4) * 4,
                       A + (size_t)(m0 + row) * HSZ + k0 + lq * 4);
            CP_ASYNC16(sb + (uint32_t)(row * SMPAD + lq * 4) * 4,
                       W + (size_t)(n0 + row) * HSZ + k0 + lq * 4);
        }
        CP_COMMIT();
        CPWAIT(0);
        __syncthreads();

#pragma unroll
        for (int s = 0; s < 4; s++) {
            const int kc = s * 8 + tig;
            uint32_t af[2][4];
#pragma unroll
            for (int mt = 0; mt < 2; mt++) {
                const int r0 = (wm * 32 + mt * 16 + g) * SMPAD;
                af[mt][0] = f2tf32(smA[r0 + kc]);
                af[mt][1] = f2tf32(smA[r0 + 8 * SMPAD + kc]);
                af[mt][2] = f2tf32(smA[r0 + kc + 4]);
                af[mt][3] = f2tf32(smA[r0 + 8 * SMPAD + kc + 4]);
            }
#pragma unroll
            for (int nt = 0; nt < 8; nt++) {
                const int nr = (wn * 64 + nt * 8 + g) * SMPAD;
                uint32_t b0 = f2tf32(smB[nr + kc]);
                uint32_t b1 = f2tf32(smB[nr + kc + 4]);
#pragma unroll
                for (int mt = 0; mt < 2; mt++)
                    mma_tf32(acc[mt][nt][0], acc[mt][nt][1], acc[mt][nt][2], acc[mt][nt][3],
                             af[mt][0], af[mt][1], af[mt][2], af[mt][3], b0, b1);
            }
        }
        __syncthreads();
    }

    float* stage = smA;
    const int m_lane = tid & 63;
    const int n_off  = tid >> 6;
#pragma unroll 1
    for (int ci = 0; ci < 4; ci++) {
        if (wn == (ci >> 1)) {
            const int ntb = (ci & 1) * 4;
#pragma unroll
            for (int mt = 0; mt < 2; mt++) {
                const int r0 = wm * 32 + mt * 16 + g;
#pragma unroll
                for (int nn = 0; nn < 4; nn++) {
                    const int nt = ntb + nn;
                    const int nl = nn * 8 + 2 * tig;
                    stage[r0 * 33 + nl]           = acc[mt][nt][0];
                    stage[r0 * 33 + nl + 1]       = acc[mt][nt][1];
                    stage[(r0 + 8) * 33 + nl]     = acc[mt][nt][2];
                    stage[(r0 + 8) * 33 + nl + 1] = acc[mt][nt][3];
                }
            }
        }
        __syncthreads();
#pragma unroll
        for (int p = 0; p < 8; p++) {
            const int nlc = p * 4 + n_off;
            const int ng  = n0 + ci * 32 + nlc;
            const float bias = __ldg(bi + ng) + __ldg(bh + ng);
#pragma unroll
            for (int half = 0; half < 2; half++) {
                const int m  = m_lane + half * 64;
                const int mg = m0 + m;
                C[((size_t)(mg >> 6) * G3 + ng) * BATCH + (mg & 63)] =
                    stage[m * 33 + nlc] + bias;
            }
        }
        __syncthreads();
    }
}

// ---------------------------------------------------------------------------
// Fused persistent recurrence: 128 CTAs x 256 threads = 2 warp-groups x 4.
// Stage s: layer0 step s (R0@h0_{s-1} + gx0[s]) and layer1 step s-1
// (W1@h0_{s-1} + R1@h1_{s-2} + bias1), 513 stages.
// Group g owns K-half [512g,512g+512) of BOTH h0 and h1 (8 chunks of 4KB per
// warp). Each warp streams ITS OWN disjoint A-fragment slice through private
// 2x4KB buffers -> only __syncwarp inside the chunk loop.
// grp0: layer0 reduce+epilogue; grp1: layer1 reduce+epilogue (+ out stores).
// Smem: 144KB weights + 8 warps x 8KB bufs + 12KB scratch = 220KB.
// ---------------------------------------------------------------------------
__global__ __launch_bounds__(256) void fused_kernel(
    const float* __restrict__ gx,   // [T][3072][64] layer0 input gates
    const float* __restrict__ R0,
    const float* __restrict__ f0,
    const float* __restrict__ W1,
    const float* __restrict__ R1,
    const float* __restrict__ bi1,
    const float* __restrict__ bh1,
    const float* __restrict__ f1,
    float* __restrict__ out)        // [T*B*H][h0f][h1f][c0f][c1f]
{
    extern __shared__ __align__(16) char s_dyn[];
    __half* Rsh = (__half*)s_dyn;               // 3 x 49152 B (R0, W1, R1)
    char*   Asm = s_dyn + 147456;               // 8 warps x 2 bufs x 4096 B
    float*  red = (float*)(s_dyn + 147456 + 65536);  // 12288 B scratch

    const int tid  = threadIdx.x;
    const int wid  = tid >> 5;
    const int grp  = wid >> 2;          // warp-group 0/1
    const int wm   = wid & 3;
    const int gtid = tid & 127;
    const int lane = tid & 31;
    const int g    = lane >> 2;
    const int tig  = lane & 3;
    const int bid  = blockIdx.x;
    const int colbase = bid * 8;
    const int gb   = grp * 4;           // first chunk (of 8) of this group

    if (tid == 0) g_flags[bid * 32] = 0;

    // ---- Load R0, W1, R1 slices -> B-fragment-order fp16 smem, once ----
    {
        const float* Ws[3] = {R0, W1, R1};
#pragma unroll 1
        for (int m = 0; m < 3; m++) {
            __half* dst0 = Rsh + (size_t)m * 24576;
            for (int v = tid; v < 6144; v += 256) {
                const int n  = v >> 8;
                const int k  = (v & 255) * 4;
                const int nt = n >> 3, nloc = n & 7;
                const int row = nt * HSZ + colbase + nloc;
                float4 w = *(const float4*)(Ws[m] + (size_t)row * HSZ + k);
                const int kb = k >> 4, kin = k & 15;
                const int t0 = (kin & 7) >> 1;
                const int hi = kin >> 3;
                __half* base = dst0 + (((kb * 3 + nt) * 32 + nloc * 4) * 4 + hi * 2);
                *(__half2*)(base + (t0    ) * 4) = __floats2half2_rn(w.x, w.y);
                *(__half2*)(base + (t0 + 1) * 4) = __floats2half2_rn(w.z, w.w);
            }
        }
    }

    grid_sync_atomic();   // flag resets + weights visible/done

    const int r0 = wm * 16 + g;
    const int r1 = r0 + 8;
    const int c0g = colbase + 2 * tig;
    const int c1g = c0g + 1;
    const float* fsrc = (grp == 0) ? f0 : f1;
    const float fga = sigf(__ldg(fsrc + c0g));
    const float fgb = sigf(__ldg(fsrc + c1g));
    float cs00 = 0.f, cs01 = 0.f, cs10 = 0.f, cs11 = 0.f;   // own layer's cell
    float bI0 = 0.f, bI1 = 0.f, bO0 = 0.f, bO1 = 0.f, bZ0 = 0.f, bZ1 = 0.f;
    if (grp == 1) {
        bI0 = __ldg(bi1 + c0g) + __ldg(bh1 + c0g);
        bI1 = __ldg(bi1 + c1g) + __ldg(bh1 + c1g);
        bO0 = __ldg(bi1 + HSZ + c0g) + __ldg(bh1 + HSZ + c0g);
        bO1 = __ldg(bi1 + HSZ + c1g) + __ldg(bh1 + HSZ + c1g);
        bZ0 = __ldg(bi1 + 2 * HSZ + c0g) + __ldg(bh1 + 2 * HSZ + c0g);
        bZ1 = __ldg(bi1 + 2 * HSZ + c1g) + __ldg(bh1 + 2 * HSZ + c1g);
    }

    const uint32_t hsA  = smem_u32(Asm);
    const uint32_t wbuf = hsA + (uint32_t)wid * 8192;          // warp-private
    const uint32_t a_lm = wbuf + (uint32_t)(lane * 16);        // + buf*4096 + blk*512
    const int wp = (colbase >> 4) * 1024 + wm * 256 + lane * 8
                 + ((colbase >> 3) & 1) * 4;
    // per-warp global A-slice offset within a chunk (bytes)
    const uint32_t gslice = (uint32_t)(wm * 512 + lane * 16);

    // Per-warp copy: this warp's 4KB slice of chunk cidx (8 blks x 512B)
#define ISSUEW(srcp, cidx, buf) do {                                            \
        const char* s_ = (const char*)(srcp) + (size_t)(cidx) * 16384 + gslice; \
        uint32_t d_ = wbuf + (uint32_t)(buf) * 4096 + (uint32_t)(lane * 16);    \
        _Pragma("unroll")                                                       \
        for (int j_ = 0; j_ < 8; j_++)                                          \
            CP_ASYNC_CG16(d_ + j_ * 512, s_ + j_ * 2048);                       \
        CP_COMMIT();                                                            \
    } while (0)

#pragma unroll 1
    for (int s = 0; s <= T_STEPS; s++) {
        // layer0 gx preactivations (grp0 only; early issue)
        float xi00 = 0.f, xi01 = 0.f, xi10 = 0.f, xi11 = 0.f;
        float xo00 = 0.f, xo01 = 0.f, xo10 = 0.f, xo11 = 0.f;
        float xz00 = 0.f, xz01 = 0.f, xz10 = 0.f, xz11 = 0.f;
        if (grp == 0 && s < T_STEPS) {
            const float* gxt = gx + (size_t)s * G3 * BATCH;
            xi00 = __ldcg(gxt + (size_t)c0g * BATCH + r0);
            xi01 = __ldcg(gxt + (size_t)c1g * BATCH + r0);
            xi10 = __ldcg(gxt + (size_t)c0g * BATCH + r1);
            xi11 = __ldcg(gxt + (size_t)c1g * BATCH + r1);
            xo00 = __ldcg(gxt + (size_t)(HSZ + c0g) * BATCH + r0);
            xo01 = __ldcg(gxt + (size_t)(HSZ + c1g) * BATCH + r0);
            xo10 = __ldcg(gxt + (size_t)(HSZ + c0g) * BATCH + r1);
            xo11 = __ldcg(gxt + (size_t)(HSZ + c1g) * BATCH + r1);
            xz00 = __ldcg(gxt + (size_t)(2 * HSZ + c0g) * BATCH + r0);
            xz01 = __ldcg(gxt + (size_t)(2 * HSZ + c1g) * BATCH + r0);
            xz10 = __ldcg(gxt + (size_t)(2 * HSZ + c0g) * BATCH + r1);
            xz11 = __ldcg(gxt + (size_t)(2 * HSZ + c1g) * BATCH + r1);
        }

        float a0[3][4], a1[3][4];
#pragma unroll
        for (int nt = 0; nt < 3; nt++)
#pragma unroll
            for (int r = 0; r < 4; r++) { a0[nt][r] = 0.f; a1[nt][r] = 0.f; }

        if (s >= 1) {
            const __half* h0src = g_h0s + (size_t)((s - 1) & 1) * HSLOTH;
            const __half* h1src = g_h1s + (size_t)(s & 1) * HSLOTH;
            const bool use_r0 = (s < T_STEPS);
            const bool use_r1 = (s >= 2);
            ISSUEW(h0src, gb + 0, 0);
            ISSUEW(h0src, gb + 1, 1);
#pragma unroll
            for (int l = 0; l < 8; l++) {
                if (l == 7) CPWAIT(0); else CPWAIT(1);
                __syncwarp();            // chunk l visible warp-wide
                const uint32_t a_ch = a_lm + (uint32_t)(l & 1) * 4096;
                const int cloc = (l < 4) ? (gb + l) : (gb + l - 4);
#pragma unroll
                for (int blk = 0; blk < 8; blk++) {
                    uint4 Af;
                    asm volatile("ld.shared.v4.b32 {%0,%1,%2,%3}, [%4];"
                                 : "=r"(Af.x), "=r"(Af.y), "=r"(Af.z), "=r"(Af.w)
                                 : "r"(a_ch + (uint32_t)(blk * 512)));
                    const int kbg = cloc * 8 + blk;
                    const char* wb = (const char*)Rsh + (size_t)kbg * 768 + lane * 8;
                    if (l < 4) {
                        if (use_r0) {
                            const uint2* bf = (const uint2*)wb;        // R0
#pragma unroll
                            for (int nt = 0; nt < 3; nt++) {
                                const uint2 Bf = bf[nt * 32];
                                mma_f16(a0[nt][0], a0[nt][1], a0[nt][2], a0[nt][3],
                                        Af.x, Af.y, Af.z, Af.w, Bf.x, Bf.y);
                            }
                        }
                        {
                            const uint2* bf = (const uint2*)(wb + 49152);  // W1
#pragma unroll
                            for (int nt = 0; nt < 3; nt++) {
                                const uint2 Bf = bf[nt * 32];
                                mma_f16(a1[nt][0], a1[nt][1], a1[nt][2], a1[nt][3],
                                        Af.x, Af.y, Af.z, Af.w, Bf.x, Bf.y);
                            }
                        }
                    } else {
                        if (use_r1) {
                            const uint2* bf = (const uint2*)(wb + 98304);  // R1
#pragma unroll
                            for (int nt = 0; nt < 3; nt++) {
                                const uint2 Bf = bf[nt * 32];
                                mma_f16(a1[nt][0], a1[nt][1], a1[nt][2], a1[nt][3],
                                        Af.x, Af.y, Af.z, Af.w, Bf.x, Bf.y);
                            }
                        }
                    }
                }
                if (l + 2 <= 7) {
                    __syncwarp();        // warp done reading buf l&1
                    const __half* nsrc = (l + 2 < 4) ? h0src : h1src;
                    const int nc = (l + 2 < 4) ? (gb + l + 2) : (gb + l - 2);
                    ISSUEW(nsrc, nc, (l & 1));
                }
            }
        }

        // ---- exchange partials: grp0 gives a1, grp1 gives a0 ----
        {
            float* d = red + (size_t)grp * 1536 + gtid * 12;
            if (grp == 0) {
#pragma unroll
                for (int nt = 0; nt < 3; nt++)
#pragma unroll
                    for (int r = 0; r < 4; r++) d[nt * 4 + r] = a1[nt][r];
            } else {
#pragma unroll
                for (int nt = 0; nt < 3; nt++)
#pragma unroll
                    for (int r = 0; r < 4; r++) d[nt * 4 + r] = a0[nt][r];
            }
            __syncthreads();
            const float* sp = red + (size_t)(1 - grp) * 1536 + gtid * 12;
            if (grp == 0) {
#pragma unroll
                for (int nt = 0; nt < 3; nt++)
#pragma unroll
                    for (int r = 0; r < 4; r++) a0[nt][r] += sp[nt * 4 + r];
            } else {
#pragma unroll
                for (int nt = 0; nt < 3; nt++)
#pragma unroll
                    for (int r = 0; r < 4; r++) a1[nt][r] += sp[nt * 4 + r];
            }
        }

        // ---- epilogues (parallel) ----
        float h00 = 0.f, h01 = 0.f, h10 = 0.f, h11 = 0.f;
        bool wrote = false;
        if (grp == 0 && s < T_STEPS) {        // layer 0 step s
            const float i00 = sigf(a0[0][0] + xi00), i01 = sigf(a0[0][1] + xi01);
            const float i10 = sigf(a0[0][2] + xi10), i11 = sigf(a0[0][3] + xi11);
            const float o00 = sigf(a0[1][0] + xo00), o01 = sigf(a0[1][1] + xo01);
            const float o10 = sigf(a0[1][2] + xo10), o11 = sigf(a0[1][3] + xo11);
            const float z00 = sigf(a0[2][0] + xz00), z01 = sigf(a0[2][1] + xz01);
            const float z10 = sigf(a0[2][2] + xz10), z11 = sigf(a0[2][3] + xz11);
            cs00 = cs00 * fga + z00 - i00;
            cs01 = cs01 * fgb + z01 - i01;
            cs10 = cs10 * fga + z10 - i10;
            cs11 = cs11 * fgb + z11 - i11;
            h00 = sigf(cs00) - o00;
            h01 = sigf(cs01) - o01;
            h10 = sigf(cs10) - o10;
            h11 = sigf(cs11) - o11;
            __half2 p0 = __floats2half2_rn(h00, h01);
            __half2 p1 = __floats2half2_rn(h10, h11);
            uint2 pk;
            pk.x = *(unsigned*)&p0;
            pk.y = *(unsigned*)&p1;
            __stcg((uint2*)(g_h0s + (size_t)(s & 1) * HSLOTH + wp), pk);
            wrote = true;
        }
        if (grp == 1 && s >= 1) {             // layer 1 step s-1
            const float i00 = sigf(a1[0][0] + bI0), i01 = sigf(a1[0][1] + bI1);
            const float i10 = sigf(a1[0][2] + bI0), i11 = sigf(a1[0][3] + bI1);
            const float o00 = sigf(a1[1][0] + bO0), o01 = sigf(a1[1][1] + bO1);
            const float o10 = sigf(a1[1][2] + bO0), o11 = sigf(a1[1][3] + bO1);
            const float z00 = sigf(a1[2][0] + bZ0), z01 = sigf(a1[2][1] + bZ1);
            const float z10 = sigf(a1[2][2] + bZ0), z11 = sigf(a1[2][3] + bZ1);
            cs00 = cs00 * fga + z00 - i00;
            cs01 = cs01 * fgb + z01 - i01;
            cs10 = cs10 * fga + z10 - i10;
            cs11 = cs11 * fgb + z11 - i11;
            h00 = sigf(cs00) - o00;
            h01 = sigf(cs01) - o01;
            h10 = sigf(cs10) - o10;
            h11 = sigf(cs11) - o11;
            __half2 p0 = __floats2half2_rn(h00, h01);
            __half2 p1 = __floats2half2_rn(h10, h11);
            uint2 pk;
            pk.x = *(unsigned*)&p0;
            pk.y = *(unsigned*)&p1;
            __stcg((uint2*)(g_h1s + (size_t)((s - 1) & 1) * HSLOTH + wp), pk);
            wrote = true;
        }

        // ---- release + non-consumed outputs + poll ----
        if (s < T_STEPS) {
            __syncthreads();                  // both slots stored CTA-wide
            if (tid == 0) st_rel(&g_flags[bid * 32], (unsigned)(s + 1));
        }
        if (grp == 1 && wrote) {
            float* hbt = out + (size_t)(s - 1) * BH;
            __stcg((float2*)(hbt + (size_t)r0 * HSZ + c0g), make_float2(h00, h01));
            __stcg((float2*)(hbt + (size_t)r1 * HSZ + c0g), make_float2(h10, h11));
        }
        if (grp == 0 && s == T_STEPS - 1) {
            float* hf = out + TBH;            // h0 final
            float* cf = out + TBH + 2 * BH;   // c0 final
            *(float2*)(hf + (size_t)r0 * HSZ + c0g) = make_float2(h00, h01);
            *(float2*)(hf + (size_t)r1 * HSZ + c0g) = make_float2(h10, h11);
            *(float2*)(cf + (size_t)r0 * HSZ + c0g) = make_float2(cs00, cs01);
            *(float2*)(cf + (size_t)r1 * HSZ + c0g) = make_float2(cs10, cs11);
        }
        if (grp == 1 && s == T_STEPS) {
            float* hf = out + TBH + BH;       // h1 final
            float* cf = out + TBH + 3 * BH;   // c1 final
            *(float2*)(hf + (size_t)r0 * HSZ + c0g) = make_float2(h00, h01);
            *(float2*)(hf + (size_t)r1 * HSZ + c0g) = make_float2(h10, h11);
            *(float2*)(cf + (size_t)r0 * HSZ + c0g) = make_float2(cs00, cs01);
            *(float2*)(cf + (size_t)r1 * HSZ + c0g) = make_float2(cs10, cs11);
        }
        if (s < T_STEPS) {
            if (tid < NB) {
                const unsigned val = (unsigned)(s + 1);
                while (ld_acq(&g_flags[tid * 32]) < val) { }
            }
            __syncthreads();
        }
    }
#undef ISSUEW
}

// ---------------------------------------------------------------------------
extern "C" void kernel_launch(void* const* d_in, const int* in_sizes, int n_in,
                              void* d_out, int out_size)
{
    const float* x   = (const float*)d_in[0];
    const float* W0  = (const float*)d_in[1];
    const float* R0  = (const float*)d_in[2];
    const float* bi0 = (const float*)d_in[3];
    const float* bh0 = (const float*)d_in[4];
    const float* f0  = (const float*)d_in[5];
    const float* W1  = (const float*)d_in[6];
    const float* R1  = (const float*)d_in[7];
    const float* bi1 = (const float*)d_in[8];
    const float* bh1 = (const float*)d_in[9];
    const float* f1  = (const float*)d_in[10];
    float* out = (float*)d_out;

    float* gx;
    cudaGetSymbolAddress((void**)&gx, g_gx);

    const int FSMEM = 147456 + 65536 + 12288;   // 225280 B
    cudaFuncSetAttribute(fused_kernel,
                         cudaFuncAttributeMaxDynamicSharedMemorySize, FSMEM);

    dim3 ggrid(G3 / 128, (T_STEPS * BATCH) / 128);   // (24, 256)

    gemm_tf32_kernel<<<ggrid, 256>>>(x, W0, bi0, bh0, gx);
    fused_kernel<<<NB, 256, FSMEM>>>(gx, R0, f0, W1, R1, bi1, bh1, f1, out);
}